// round 6
// baseline (speedup 1.0000x reference)
#include <cuda_runtime.h>
#include <cuda_bf16.h>
#include <cstdint>

// Problem constants
#define BATCH 16384
#define NN    1024
#define NI    128
#define NO    64
#define REFRACTORY 0.9f

// Tiling
#define MT       64             // batch rows per CTA
#define KC       64             // k per chunk
#define NCHUNK   (NN / KC)      // 16
#define NTHREADS 256            // 8 warps: 2 m-groups x 4 n-groups
#define STAGES   5

// ---- dynamic smem layout ----
// [0,256)  bias[64] f32   [256,512) act[64] i32
// [1024+)  ring of STAGES A-stages, 16KB each (fp32, swizzled)
#define SMEM_BIAS    0
#define SMEM_ACT     256
#define SMEM_BUF0    1024
#define STAGE_STRIDE 16384
#define SMEM_TOTAL   (SMEM_BUF0 + STAGES * STAGE_STRIDE)   // 82944

// Pre-packed, tf32-rounded, refractory-folded weight slice.
// Layout: [chunk][warpn(4)][i(8)][lane(32)][4 floats] — each warp's chunk
// slice is 8 contiguous 512B segments -> 8 coalesced LDG.128 per chunk.
// Value (i,lane,j): v = i*4+j; ks=v>>2; nf=(v>>1)&1; p=v&1;
//   k = chunk*64 + ks*8 + (lane&3) + p*4;  n = warpn*16 + nf*8 + (lane>>2)
__device__ __align__(16) float g_Bpack[NCHUNK][4][8][32][4];

__device__ __forceinline__ uint32_t smem_u32(const void* p) {
    uint32_t a;
    asm("{ .reg .u64 t; cvta.to.shared.u64 t, %1; cvt.u32.u64 %0, t; }" : "=r"(a) : "l"(p));
    return a;
}
__device__ __forceinline__ void ldm_x4(uint32_t* r, uint32_t addr) {
    asm volatile("ldmatrix.sync.aligned.m8n8.x4.shared.b16 {%0,%1,%2,%3}, [%4];"
                 : "=r"(r[0]), "=r"(r[1]), "=r"(r[2]), "=r"(r[3]) : "r"(addr));
}
__device__ __forceinline__ void mma_tf32(float* d, const uint32_t* a, uint32_t b0, uint32_t b1) {
    asm volatile(
        "mma.sync.aligned.m16n8k8.row.col.f32.tf32.tf32.f32 "
        "{%0,%1,%2,%3}, {%4,%5,%6,%7}, {%8,%9}, {%0,%1,%2,%3};"
        : "+f"(d[0]), "+f"(d[1]), "+f"(d[2]), "+f"(d[3])
        : "r"(a[0]), "r"(a[1]), "r"(a[2]), "r"(a[3]), "r"(b0), "r"(b1));
}
__device__ __forceinline__ uint32_t cvt_tf32(uint32_t x) {
    uint32_t d;
    asm("cvt.rna.tf32.f32 %0, %1;" : "=r"(d) : "f"(__uint_as_float(x)));
    return d;
}
__device__ __forceinline__ void cp_async16(uint32_t smem_addr, const void* gptr) {
    asm volatile("cp.async.cg.shared.global [%0], [%1], 16;"
                 :: "r"(smem_addr), "l"(gptr) : "memory");
}
#define CP_COMMIT() asm volatile("cp.async.commit_group;" ::: "memory")
#define CP_WAIT3()  asm volatile("cp.async.wait_group 3;" ::: "memory")

// A stage layout: 64 rows x 16 units(16B). Two 8KB halves (u<8 / u>=8).
// off = (u>>3)*8192 + row*128 + ((u&7)^(row&7))*16 — conflict-free for both
// cp.async stores and ldmatrix reads.
__device__ __forceinline__ uint32_t a_off(int row, int u) {
    return (uint32_t)((u >> 3) * 8192 + row * 128 + (((u & 7) ^ (row & 7)) << 4));
}

// ---------------- prep: round + fold + pack weight slice ----------------
__global__ void prep_kernel(const float* __restrict__ W) {
    int idx = blockIdx.x * blockDim.x + threadIdx.x;   // 0..65535
    if (idx >= NCHUNK * 4 * 8 * 32 * 4) return;
    int j     = idx & 3;
    int lane  = (idx >> 2) & 31;
    int i     = (idx >> 7) & 7;
    int warpn = (idx >> 10) & 3;
    int chunk = idx >> 12;
    int v  = i * 4 + j;
    int ks = v >> 2, nf = (v >> 1) & 1, p = v & 1;
    int k = chunk * 64 + ks * 8 + (lane & 3) + p * 4;
    int n = warpn * 16 + nf * 8 + (lane >> 2);
    float f = (k >= NI && k < NN - NO) ? REFRACTORY : 1.0f;
    float val = W[(size_t)k * NN + (NN - NO) + n] * f;
    ((float*)g_Bpack)[idx] = __uint_as_float(cvt_tf32(__float_as_uint(val)));
}

// ---------------- activation ----------------
__device__ __forceinline__ float activate(float x, int a) {
    if (a == 0) return fmaxf(x, 0.0f);
    if (a == 1) { float r; asm("tanh.approx.f32 %0, %1;" : "=f"(r) : "f"(x)); return r; }
    if (a == 2) {
        float e, r;
        asm("ex2.approx.f32 %0, %1;" : "=f"(e) : "f"(-1.4426950408889634f * x));
        asm("rcp.approx.f32 %0, %1;" : "=f"(r) : "f"(1.0f + e));
        return r;
    }
    return x;
}

// ---------------- main kernel ----------------
__global__ void __launch_bounds__(NTHREADS, 2)
nn_tf32_kernel(const float* __restrict__ prev,    // [B, N]
               const float* __restrict__ inp,     // [B, I]
               const float* __restrict__ biases,  // [N]
               const int*   __restrict__ act,     // [N]
               float* __restrict__ out)           // [B, O]
{
    extern __shared__ unsigned char smem[];
    const uint32_t sb = smem_u32(smem);
    const int tid   = threadIdx.x;
    const int lane  = tid & 31;
    const int wid   = tid >> 5;
    const int warpm = wid >> 2;   // 0..1 (32 rows each)
    const int warpn = wid & 3;    // 0..3 (16 cols each)
    const int row0  = blockIdx.x * MT;

    float* sbias = (float*)(smem + SMEM_BIAS);
    int*   sact  = (int*)(smem + SMEM_ACT);
    if (tid < NO) {
        sbias[tid] = biases[NN - NO + tid];
        sact[tid]  = act[NN - NO + tid];
    }

    // issue A loads for chunk c into stage s (one commit group per call site)
    auto issueA = [&](int c, int s) {
        const uint32_t stage = sb + SMEM_BUF0 + s * STAGE_STRIDE;
        const float* src;
        int ldx;
        if (c < 2) { src = inp  + (size_t)row0 * NI + c * KC; ldx = NI; }
        else       { src = prev + (size_t)row0 * NN + c * KC; ldx = NN; }
#pragma unroll
        for (int i = 0; i < 4; ++i) {
            int g = tid + i * NTHREADS;          // 0..1023
            int row = g >> 4, u = g & 15;
            cp_async16(stage + a_off(row, u), src + (size_t)row * ldx + u * 4);
        }
    };

    float acc[2][2][4];
#pragma unroll
    for (int mt = 0; mt < 2; ++mt)
#pragma unroll
        for (int nf = 0; nf < 2; ++nf)
#pragma unroll
            for (int i = 0; i < 4; ++i) acc[mt][nf][i] = 0.0f;

    // prologue: A chunks 0..3 into stages 0..3 (4 groups)
    issueA(0, 0); CP_COMMIT();
    issueA(1, 1); CP_COMMIT();
    issueA(2, 2); CP_COMMIT();
    issueA(3, 3); CP_COMMIT();

    // B chunk 0 into registers (L2-resident after first wave)
    const uint4* bbase = (const uint4*)&g_Bpack[0][warpn][0][lane][0];
    const int bstride = (4 * 8 * 32 * 4) / 4;   // uint4s per chunk = 1024
    uint4 bq[8], bnext[8];
#pragma unroll
    for (int i = 0; i < 8; ++i) bq[i] = __ldg(bbase + i * 32);

    const int r0w = warpm * 32 + (lane & 15);
    const int uhi = lane >> 4;

    for (int c = 0; c < NCHUNK; ++c) {
        const int s = c % STAGES;
        const uint32_t stage = sb + SMEM_BUF0 + s * STAGE_STRIDE;

        // groups committed so far = 4 + c; wait <=3 pending -> chunk c ready
        CP_WAIT3();
        __syncthreads();       // all warps done with chunk c-1 -> stage (c+4)%5 free

        if (c + 4 < NCHUNK) issueA(c + 4, (c + 4) % STAGES);
        CP_COMMIT();           // (possibly empty) keeps group accounting linear

        // prefetch B for chunk c+1
        if (c + 1 < NCHUNK) {
            const uint4* bp = bbase + (c + 1) * bstride;
#pragma unroll
            for (int i = 0; i < 8; ++i) bnext[i] = __ldg(bp + i * 32);
        }

#pragma unroll
        for (int ks = 0; ks < 8; ++ks) {
            uint32_t a[2][4];
#pragma unroll
            for (int mt = 0; mt < 2; ++mt) {
                int u = 2 * ks + uhi;
                ldm_x4(a[mt], stage + a_off(r0w + mt * 16, u));
#pragma unroll
                for (int q = 0; q < 4; ++q) a[mt][q] = cvt_tf32(a[mt][q]);
            }
            uint32_t b0h = bq[ks].x, b0l = bq[ks].y;   // nf=0: p=0,1
            uint32_t b1h = bq[ks].z, b1l = bq[ks].w;   // nf=1: p=0,1
#pragma unroll
            for (int mt = 0; mt < 2; ++mt) {
                mma_tf32(acc[mt][0], a[mt], b0h, b0l);
                mma_tf32(acc[mt][1], a[mt], b1h, b1l);
            }
        }

#pragma unroll
        for (int i = 0; i < 8; ++i) bq[i] = bnext[i];
    }

    // ---- epilogue: bias + heterogeneous activation + store ----
#pragma unroll
    for (int mt = 0; mt < 2; ++mt)
#pragma unroll
        for (int nf = 0; nf < 2; ++nf) {
            int col = warpn * 16 + nf * 8 + (lane & 3) * 2;
            int rg  = row0 + warpm * 32 + mt * 16 + (lane >> 2);
            float b0 = sbias[col], b1 = sbias[col + 1];
            int   a0 = sact[col],  a1 = sact[col + 1];
            float2 o;
            o.x = activate(acc[mt][nf][0] + b0, a0);
            o.y = activate(acc[mt][nf][1] + b1, a1);
            *(float2*)(out + (size_t)rg * NO + col) = o;
            o.x = activate(acc[mt][nf][2] + b0, a0);
            o.y = activate(acc[mt][nf][3] + b1, a1);
            *(float2*)(out + (size_t)(rg + 8) * NO + col) = o;
        }
}

extern "C" void kernel_launch(void* const* d_in, const int* in_sizes, int n_in,
                              void* d_out, int out_size) {
    (void)in_sizes; (void)n_in; (void)out_size;
    const float* prev   = (const float*)d_in[0];  // [16384,1024]
    const float* inp    = (const float*)d_in[1];  // [16384,128]
    const float* W      = (const float*)d_in[2];  // [1024,1024]
    const float* biases = (const float*)d_in[3];  // [1024]
    const int*   act    = (const int*)d_in[4];    // [1024]
    float* out = (float*)d_out;                   // [16384,64]

    cudaFuncSetAttribute(nn_tf32_kernel, cudaFuncAttributeMaxDynamicSharedMemorySize, SMEM_TOTAL);

    prep_kernel<<<256, 256>>>(W);
    nn_tf32_kernel<<<BATCH / MT, NTHREADS, SMEM_TOTAL>>>(prev, inp, biases, act, out);
}